// round 5
// baseline (speedup 1.0000x reference)
#include <cuda_runtime.h>

// Problem constants (fixed shapes for ClusterLoss_82317343195278)
#define NROWS 65536
#define DLAT  64
#define KC    64
#define DDATA 512
#define NB    256   // blocks in kmeans kernel
#define TPB   4     // 64-row tiles per block: NB*TPB*64 == NROWS
#define NITERS 10

// Scratch (static device globals — no allocation allowed)
__device__ __align__(16) float g_CT[DLAT * KC];        // centroids, TRANSPOSED [d][k]
__device__ __align__(16) float g_x2[NROWS];            // per-row squared norms of enc
__device__ __align__(16) float g_partC[NB][KC * DLAT]; // per-block partial r^T@enc [b][k*64+d]
__device__ __align__(16) float g_partR[NB][KC];        // per-block partial colsum(r)
__device__ float g_lossSum;
__device__ float g_decSum;

// ---------------------------------------------------------------------------
// Init: x2 per row, C = enc[:K] (stored transposed), zero accumulators
// ---------------------------------------------------------------------------
__global__ void init_kernel(const float* __restrict__ enc) {
    int g = blockIdx.x * blockDim.x + threadIdx.x;  // one thread per row
    const float4* p = reinterpret_cast<const float4*>(enc) + (size_t)g * (DLAT / 4);
    float s = 0.f;
#pragma unroll
    for (int i = 0; i < DLAT / 4; i++) {
        float4 v = p[i];
        s += v.x * v.x + v.y * v.y + v.z * v.z + v.w * v.w;
    }
    g_x2[g] = s;
    if (g < KC * DLAT) {
        int k = g / DLAT, d = g % DLAT;
        g_CT[d * KC + k] = enc[g];
    }
    if (g == 0) { g_lossSum = 0.f; g_decSum = 0.f; }
}

// ---------------------------------------------------------------------------
// Decoder loss: sum((X - decoding)^2) — streaming, HBM-bound
// ---------------------------------------------------------------------------
__global__ void decoder_kernel(const float4* __restrict__ X,
                               const float4* __restrict__ Dc, int n4) {
    int i = blockIdx.x * blockDim.x + threadIdx.x;
    int stride = gridDim.x * blockDim.x;
    float s = 0.f;
    for (; i < n4; i += stride) {
        float4 a = X[i], b = Dc[i];
        float dx = a.x - b.x, dy = a.y - b.y, dz = a.z - b.z, dw = a.w - b.w;
        s += dx * dx + dy * dy + dz * dz + dw * dw;
    }
    __shared__ float red[256];
    red[threadIdx.x] = s;
    __syncthreads();
#pragma unroll
    for (int o = 128; o > 0; o >>= 1) {
        if (threadIdx.x < o) red[threadIdx.x] += red[threadIdx.x + o];
        __syncthreads();
    }
    if (threadIdx.x == 0) atomicAdd(&g_decSum, red[0]);
}

// ---------------------------------------------------------------------------
// One soft-kmeans iteration. Each block: 4 tiles of 64 rows.
// Per tile: G = encTile @ C^T (4x4 register frags), clamped d2, softmax over k
// (16-lane shuffle reduce: one row's 64 k-values live in one half-warp),
// r -> smem (reusing C buffer), partial r^T@encTile accumulated in registers.
// Per-block partials go to scratch slots (deterministic, no atomic contention).
// ---------------------------------------------------------------------------
__global__ void __launch_bounds__(256, 2)
kmeans_iter(const float* __restrict__ enc, int doLoss) {
    __shared__ __align__(16) float sA[64 * 64];  // C^T [d][k], later r [row][k]
    __shared__ __align__(16) float sE[64 * 64];  // enc tile [row][d]
    __shared__ float sc2[KC];
    __shared__ float sred[256];

    const int tid = threadIdx.x;
    const int tx = tid & 15, ty = tid >> 4;
    const int k0 = tx * 4, r0 = ty * 4;

    // load C^T once for c2; reloaded per tile since sA is reused for r
    for (int idx = tid; idx < 64 * 64; idx += 256) sA[idx] = g_CT[idx];
    __syncthreads();
    if (tid < KC) {
        float s = 0.f;
#pragma unroll 8
        for (int d = 0; d < DLAT; d++) { float c = sA[d * 64 + tid]; s += c * c; }
        sc2[tid] = s;
    }

    float cacc[4][4];
#pragma unroll
    for (int j = 0; j < 4; j++)
#pragma unroll
        for (int i = 0; i < 4; i++) cacc[j][i] = 0.f;
    float rsum[4] = {0.f, 0.f, 0.f, 0.f};
    float lossAcc = 0.f;

    for (int t = 0; t < TPB; t++) {
        const int rowBase = (blockIdx.x * TPB + t) * 64;
        if (t > 0) {  // restore C^T (sA held r from previous tile)
            for (int idx = tid; idx < 64 * 64; idx += 256) sA[idx] = g_CT[idx];
        }
        for (int idx = tid; idx < 64 * 64; idx += 256)
            sE[idx] = enc[(size_t)rowBase * DLAT + idx];
        __syncthreads();

        // ---- GEMM1: G[i][j] = dot(enc[r0+i], C[k0+j]) ----
        float G[4][4];
#pragma unroll
        for (int i = 0; i < 4; i++)
#pragma unroll
            for (int j = 0; j < 4; j++) G[i][j] = 0.f;
#pragma unroll 4
        for (int d = 0; d < 64; d++) {
            float4 c = *(const float4*)&sA[d * 64 + k0];
            float e0 = sE[(r0 + 0) * 64 + d];
            float e1 = sE[(r0 + 1) * 64 + d];
            float e2 = sE[(r0 + 2) * 64 + d];
            float e3 = sE[(r0 + 3) * 64 + d];
            G[0][0] += e0 * c.x; G[0][1] += e0 * c.y; G[0][2] += e0 * c.z; G[0][3] += e0 * c.w;
            G[1][0] += e1 * c.x; G[1][1] += e1 * c.y; G[1][2] += e1 * c.z; G[1][3] += e1 * c.w;
            G[2][0] += e2 * c.x; G[2][1] += e2 * c.y; G[2][2] += e2 * c.z; G[2][3] += e2 * c.w;
            G[3][0] += e3 * c.x; G[3][1] += e3 * c.y; G[3][2] += e3 * c.z; G[3][3] += e3 * c.w;
        }
        __syncthreads();  // done reading sA as C^T

        // ---- d2 + softmax + (last iter) loss; write r into sA ----
#pragma unroll
        for (int i = 0; i < 4; i++) {
            float x2v = g_x2[rowBase + r0 + i];
            float d2[4], rr[4];
#pragma unroll
            for (int j = 0; j < 4; j++) {
                float v = x2v + sc2[k0 + j] - 2.f * G[i][j];
                d2[j] = v > 0.f ? v : 0.f;
            }
            float mn = fminf(fminf(d2[0], d2[1]), fminf(d2[2], d2[3]));
#pragma unroll
            for (int o = 1; o < 16; o <<= 1)
                mn = fminf(mn, __shfl_xor_sync(0xffffffffu, mn, o));
            float es = 0.f;
#pragma unroll
            for (int j = 0; j < 4; j++) { rr[j] = __expf(mn - d2[j]); es += rr[j]; }
#pragma unroll
            for (int o = 1; o < 16; o <<= 1)
                es += __shfl_xor_sync(0xffffffffu, es, o);
            float inv = __fdividef(1.f, es);
            float ls = 0.f;
#pragma unroll
            for (int j = 0; j < 4; j++) { rr[j] *= inv; ls += rr[j] * d2[j]; }
            *(float4*)&sA[(r0 + i) * 64 + k0] = make_float4(rr[0], rr[1], rr[2], rr[3]);
            if (doLoss) {
#pragma unroll
                for (int o = 1; o < 16; o <<= 1)
                    ls += __shfl_xor_sync(0xffffffffu, ls, o);
                if (tx == 0) lossAcc += ls;
            }
        }
        __syncthreads();

        // ---- GEMM2: cacc[k0+j][d0+i] += sum_row r[row][k0+j]*enc[row][d0+i] ----
        const int d0 = ty * 4;
#pragma unroll 4
        for (int row = 0; row < 64; row++) {
            float4 rf = *(const float4*)&sA[row * 64 + k0];
            float4 ef = *(const float4*)&sE[row * 64 + d0];
            cacc[0][0] += rf.x * ef.x; cacc[0][1] += rf.x * ef.y; cacc[0][2] += rf.x * ef.z; cacc[0][3] += rf.x * ef.w;
            cacc[1][0] += rf.y * ef.x; cacc[1][1] += rf.y * ef.y; cacc[1][2] += rf.y * ef.z; cacc[1][3] += rf.y * ef.w;
            cacc[2][0] += rf.z * ef.x; cacc[2][1] += rf.z * ef.y; cacc[2][2] += rf.z * ef.z; cacc[2][3] += rf.z * ef.w;
            cacc[3][0] += rf.w * ef.x; cacc[3][1] += rf.w * ef.y; cacc[3][2] += rf.w * ef.z; cacc[3][3] += rf.w * ef.w;
            if (ty == 0) { rsum[0] += rf.x; rsum[1] += rf.y; rsum[2] += rf.z; rsum[3] += rf.w; }
        }
        __syncthreads();
    }

    // ---- deterministic partial writes (own slot, no contention) ----
#pragma unroll
    for (int j = 0; j < 4; j++) {
        *(float4*)&g_partC[blockIdx.x][(k0 + j) * DLAT + ty * 4] =
            make_float4(cacc[j][0], cacc[j][1], cacc[j][2], cacc[j][3]);
    }
    if (ty == 0) {
#pragma unroll
        for (int j = 0; j < 4; j++) g_partR[blockIdx.x][k0 + j] = rsum[j];
    }
    if (doLoss) {
        sred[tid] = lossAcc;
        __syncthreads();
        for (int o = 128; o > 0; o >>= 1) {
            if (tid < o) sred[tid] += sred[tid + o];
            __syncthreads();
        }
        if (tid == 0) atomicAdd(&g_lossSum, sred[0]);
    }
}

// ---------------------------------------------------------------------------
// Centroid update: C[k][d] = sum_b partC[b][k][d] / (sum_b partR[b][k] + EPS)
// 64 blocks (k) x 64 threads (d). Stores transposed into g_CT.
// ---------------------------------------------------------------------------
__global__ void update_kernel() {
    const int k = blockIdx.x;
    const int t = threadIdx.x;
    __shared__ float red[64];
    float rs = 0.f;
    for (int b = t; b < NB; b += 64) rs += g_partR[b][k];
    red[t] = rs;
    __syncthreads();
#pragma unroll
    for (int o = 32; o > 0; o >>= 1) {
        if (t < o) red[t] += red[t + o];
        __syncthreads();
    }
    const float denom = red[0] + 1e-8f;
    float acc = 0.f;
#pragma unroll 8
    for (int b = 0; b < NB; b++) acc += g_partC[b][k * DLAT + t];
    g_CT[t * KC + k] = acc / denom;
}

__global__ void finalize_kernel(float* out) {
    out[0] = g_decSum * (1.f / ((float)NROWS * (float)DDATA))
           + 0.001f * g_lossSum * (1.f / (float)NROWS);
}

// ---------------------------------------------------------------------------
extern "C" void kernel_launch(void* const* d_in, const int* in_sizes, int n_in,
                              void* d_out, int out_size) {
    const float* X   = (const float*)d_in[0];
    const float* enc = (const float*)d_in[1];
    const float* dec = (const float*)d_in[2];
    float* out = (float*)d_out;

    init_kernel<<<NROWS / 256, 256>>>(enc);

    const int n4 = NROWS * DDATA / 4;  // 8,388,608 float4s
    decoder_kernel<<<1024, 256>>>((const float4*)X, (const float4*)dec, n4);

    for (int it = 0; it < NITERS; it++) {
        kmeans_iter<<<NB, 256>>>(enc, it == NITERS - 1 ? 1 : 0);
        if (it < NITERS - 1) update_kernel<<<KC, 64>>>();
    }

    finalize_kernel<<<1, 1>>>(out);
}

// round 9
// speedup vs baseline: 1.1011x; 1.1011x over previous
#include <cuda_runtime.h>

// Problem constants (fixed shapes for ClusterLoss_82317343195278)
#define NROWS 65536
#define DLAT  64
#define KC    64
#define DDATA 512
#define NB    256   // blocks in kmeans kernel
#define TPB   4     // 64-row tiles per block: NB*TPB*64 == NROWS
#define NITERS 10

typedef unsigned long long u64;

// ---- packed f32x2 helpers (SASS FFMA2 — ptxas won't emit from C++) ----
__device__ __forceinline__ u64 ffma2(u64 a, u64 b, u64 c) {
    u64 d;
    asm("fma.rn.f32x2 %0, %1, %2, %3;" : "=l"(d) : "l"(a), "l"(b), "l"(c));
    return d;
}
__device__ __forceinline__ u64 fadd2(u64 a, u64 b) {
    u64 d;
    asm("add.rn.f32x2 %0, %1, %2;" : "=l"(d) : "l"(a), "l"(b));
    return d;
}
__device__ __forceinline__ u64 pack2(float x, float y) {
    u64 r;
    asm("mov.b64 %0, {%1, %2};" : "=l"(r) : "f"(x), "f"(y));
    return r;
}
__device__ __forceinline__ float2 unpack2(u64 v) {
    float2 f;
    asm("mov.b64 {%0, %1}, %2;" : "=f"(f.x), "=f"(f.y) : "l"(v));
    return f;
}

// Scratch (static device globals — no allocation allowed)
// g_CP: centroids in d-pair-interleaved layout:
//   C[k][d]  lives at  g_CP[(d>>1)*128 + k*2 + (d&1)]
// so (C[k][d], C[k][d+1]) is one aligned 8-byte f32x2 operand, and the four
// pairs for k0..k0+3 are 8 consecutive floats (one ulonglong2 LDS.128).
__device__ __align__(16) float g_CP[DLAT / 2 * KC * 2];
__device__ __align__(16) float g_x2[NROWS];
__device__ __align__(16) float g_partC[NB][KC * DLAT]; // [b][k*64+d]
__device__ __align__(16) float g_partR[NB][KC];
__device__ float g_lossSum;
__device__ float g_decSum;

// ---------------------------------------------------------------------------
// Init: x2 per row, C = enc[:K] (packed layout), zero accumulators
// ---------------------------------------------------------------------------
__global__ void init_kernel(const float* __restrict__ enc) {
    int g = blockIdx.x * blockDim.x + threadIdx.x;  // one thread per row
    const float4* p = reinterpret_cast<const float4*>(enc) + (size_t)g * (DLAT / 4);
    float s = 0.f;
#pragma unroll
    for (int i = 0; i < DLAT / 4; i++) {
        float4 v = p[i];
        s += v.x * v.x + v.y * v.y + v.z * v.z + v.w * v.w;
    }
    g_x2[g] = s;
    if (g < KC * DLAT) {
        int k = g / DLAT, d = g % DLAT;
        g_CP[(d >> 1) * 128 + k * 2 + (d & 1)] = enc[g];
    }
    if (g == 0) { g_lossSum = 0.f; g_decSum = 0.f; }
}

// ---------------------------------------------------------------------------
// Decoder loss: sum((X - decoding)^2) — streaming, HBM-bound
// ---------------------------------------------------------------------------
__global__ void decoder_kernel(const float4* __restrict__ X,
                               const float4* __restrict__ Dc, int n4) {
    int i = blockIdx.x * blockDim.x + threadIdx.x;
    int stride = gridDim.x * blockDim.x;
    float s = 0.f;
    for (; i < n4; i += stride) {
        float4 a = X[i], b = Dc[i];
        float dx = a.x - b.x, dy = a.y - b.y, dz = a.z - b.z, dw = a.w - b.w;
        s += dx * dx + dy * dy + dz * dz + dw * dw;
    }
    __shared__ float red[256];
    red[threadIdx.x] = s;
    __syncthreads();
#pragma unroll
    for (int o = 128; o > 0; o >>= 1) {
        if (threadIdx.x < o) red[threadIdx.x] += red[threadIdx.x + o];
        __syncthreads();
    }
    if (threadIdx.x == 0) atomicAdd(&g_decSum, red[0]);
}

// ---------------------------------------------------------------------------
// One soft-kmeans iteration with packed-f32x2 GEMM loops.
// ---------------------------------------------------------------------------
__global__ void __launch_bounds__(256, 2)
kmeans_iter(const float* __restrict__ enc, int doLoss) {
    __shared__ __align__(16) float sCp[64 * 64];  // packed C^T; later r [row][k]
    __shared__ __align__(16) float sE[64 * 64];   // enc tile [row][d]
    __shared__ float sc2[KC];
    __shared__ float sred[256];

    const int tid = threadIdx.x;
    const int tx = tid & 15, ty = tid >> 4;
    const int k0 = tx * 4, r0 = ty * 4, d0 = ty * 4;

    // load packed C (for c2 + first tile's GEMM1)
    {
        const float4* src = (const float4*)g_CP;
        float4* dst = (float4*)sCp;
        for (int i = tid; i < 1024; i += 256) dst[i] = src[i];
    }
    __syncthreads();
    if (tid < KC) {
        float s = 0.f;
#pragma unroll 8
        for (int d = 0; d < DLAT; d++) {
            float c = sCp[(d >> 1) * 128 + tid * 2 + (d & 1)];
            s += c * c;
        }
        sc2[tid] = s;  // consumed after the GEMM1 __syncthreads
    }

    u64 accP[4][2];  // r^T@enc partial: [i (d offset)][k-pair]
#pragma unroll
    for (int i = 0; i < 4; i++) { accP[i][0] = 0ULL; accP[i][1] = 0ULL; }
    u64 rsP[2] = {0ULL, 0ULL};
    float lossAcc = 0.f;

#pragma unroll 1
    for (int t = 0; t < TPB; t++) {
        const int rowBase = (blockIdx.x * TPB + t) * 64;
        if (t > 0) {  // restore packed C (sCp held r from previous tile)
            const float4* src = (const float4*)g_CP;
            float4* dst = (float4*)sCp;
            for (int i = tid; i < 1024; i += 256) dst[i] = src[i];
        }
        {
            const float4* src = (const float4*)(enc + (size_t)rowBase * DLAT);
            float4* dst = (float4*)sE;
            for (int i = tid; i < 1024; i += 256) dst[i] = src[i];
        }
        __syncthreads();

        // ---- GEMM1: Gp[i][j] accumulates (even-d, odd-d) partial dots ----
        u64 Gp[4][4];
#pragma unroll
        for (int i = 0; i < 4; i++)
#pragma unroll
            for (int j = 0; j < 4; j++) Gp[i][j] = 0ULL;
#pragma unroll 4
        for (int dp = 0; dp < 32; dp++) {
            ulonglong2 ca = *(const ulonglong2*)&sCp[dp * 128 + k0 * 2];      // k0, k0+1
            ulonglong2 cb = *(const ulonglong2*)&sCp[dp * 128 + k0 * 2 + 4];  // k0+2, k0+3
            u64 e0 = *(const u64*)&sE[(r0 + 0) * 64 + dp * 2];
            u64 e1 = *(const u64*)&sE[(r0 + 1) * 64 + dp * 2];
            u64 e2 = *(const u64*)&sE[(r0 + 2) * 64 + dp * 2];
            u64 e3 = *(const u64*)&sE[(r0 + 3) * 64 + dp * 2];
            Gp[0][0] = ffma2(e0, ca.x, Gp[0][0]); Gp[0][1] = ffma2(e0, ca.y, Gp[0][1]);
            Gp[0][2] = ffma2(e0, cb.x, Gp[0][2]); Gp[0][3] = ffma2(e0, cb.y, Gp[0][3]);
            Gp[1][0] = ffma2(e1, ca.x, Gp[1][0]); Gp[1][1] = ffma2(e1, ca.y, Gp[1][1]);
            Gp[1][2] = ffma2(e1, cb.x, Gp[1][2]); Gp[1][3] = ffma2(e1, cb.y, Gp[1][3]);
            Gp[2][0] = ffma2(e2, ca.x, Gp[2][0]); Gp[2][1] = ffma2(e2, ca.y, Gp[2][1]);
            Gp[2][2] = ffma2(e2, cb.x, Gp[2][2]); Gp[2][3] = ffma2(e2, cb.y, Gp[2][3]);
            Gp[3][0] = ffma2(e3, ca.x, Gp[3][0]); Gp[3][1] = ffma2(e3, ca.y, Gp[3][1]);
            Gp[3][2] = ffma2(e3, cb.x, Gp[3][2]); Gp[3][3] = ffma2(e3, cb.y, Gp[3][3]);
        }
        __syncthreads();  // done reading sCp as C

        // ---- d2 + softmax + (last iter) loss; write r into sCp ----
#pragma unroll
        for (int i = 0; i < 4; i++) {
            float x2v = g_x2[rowBase + r0 + i];
            float d2[4], rr[4];
#pragma unroll
            for (int j = 0; j < 4; j++) {
                float2 g = unpack2(Gp[i][j]);
                float G = g.x + g.y;
                float v = x2v + sc2[k0 + j] - 2.f * G;
                d2[j] = v > 0.f ? v : 0.f;
            }
            float mn = fminf(fminf(d2[0], d2[1]), fminf(d2[2], d2[3]));
#pragma unroll
            for (int o = 1; o < 16; o <<= 1)
                mn = fminf(mn, __shfl_xor_sync(0xffffffffu, mn, o));
            float es = 0.f;
#pragma unroll
            for (int j = 0; j < 4; j++) { rr[j] = __expf(mn - d2[j]); es += rr[j]; }
#pragma unroll
            for (int o = 1; o < 16; o <<= 1)
                es += __shfl_xor_sync(0xffffffffu, es, o);
            float inv = __fdividef(1.f, es);
            float ls = 0.f;
#pragma unroll
            for (int j = 0; j < 4; j++) { rr[j] *= inv; ls += rr[j] * d2[j]; }
            *(float4*)&sCp[(r0 + i) * 64 + k0] = make_float4(rr[0], rr[1], rr[2], rr[3]);
            if (doLoss) {
#pragma unroll
                for (int o = 1; o < 16; o <<= 1)
                    ls += __shfl_xor_sync(0xffffffffu, ls, o);
                if (tx == 0) lossAcc += ls;
            }
        }
        __syncthreads();

        // ---- GEMM2: accP[i][jp] += (e_i,e_i) * (r_{k0+2jp}, r_{k0+2jp+1}) ----
#pragma unroll 4
        for (int row = 0; row < 64; row++) {
            ulonglong2 rf = *(const ulonglong2*)&sCp[row * 64 + k0];  // (k0,k0+1),(k0+2,k0+3)
            float4 ef = *(const float4*)&sE[row * 64 + d0];
            u64 p0 = pack2(ef.x, ef.x);
            u64 p1 = pack2(ef.y, ef.y);
            u64 p2 = pack2(ef.z, ef.z);
            u64 p3 = pack2(ef.w, ef.w);
            accP[0][0] = ffma2(p0, rf.x, accP[0][0]); accP[0][1] = ffma2(p0, rf.y, accP[0][1]);
            accP[1][0] = ffma2(p1, rf.x, accP[1][0]); accP[1][1] = ffma2(p1, rf.y, accP[1][1]);
            accP[2][0] = ffma2(p2, rf.x, accP[2][0]); accP[2][1] = ffma2(p2, rf.y, accP[2][1]);
            accP[3][0] = ffma2(p3, rf.x, accP[3][0]); accP[3][1] = ffma2(p3, rf.y, accP[3][1]);
            if (ty == 0) { rsP[0] = fadd2(rsP[0], rf.x); rsP[1] = fadd2(rsP[1], rf.y); }
        }
        __syncthreads();
    }

    // ---- deterministic partial writes (own slot, no contention) ----
#pragma unroll
    for (int jp = 0; jp < 2; jp++) {
        float2 a0 = unpack2(accP[0][jp]);
        float2 a1 = unpack2(accP[1][jp]);
        float2 a2 = unpack2(accP[2][jp]);
        float2 a3 = unpack2(accP[3][jp]);
        *(float4*)&g_partC[blockIdx.x][(k0 + 2 * jp + 0) * DLAT + d0] =
            make_float4(a0.x, a1.x, a2.x, a3.x);
        *(float4*)&g_partC[blockIdx.x][(k0 + 2 * jp + 1) * DLAT + d0] =
            make_float4(a0.y, a1.y, a2.y, a3.y);
    }
    if (ty == 0) {
        float2 s0 = unpack2(rsP[0]);
        float2 s1 = unpack2(rsP[1]);
        *(float4*)&g_partR[blockIdx.x][k0] = make_float4(s0.x, s0.y, s1.x, s1.y);
    }
    if (doLoss) {
        sred[tid] = lossAcc;
        __syncthreads();
        for (int o = 128; o > 0; o >>= 1) {
            if (tid < o) sred[tid] += sred[tid + o];
            __syncthreads();
        }
        if (tid == 0) atomicAdd(&g_lossSum, sred[0]);
    }
}

// ---------------------------------------------------------------------------
// Centroid update, high-occupancy: 256 blocks x 256 threads.
// Block (k = bid>>2, d0 = (bid&3)*16) produces 16 outputs; 16 threads/output.
// Coalesced 64B reads; smem tree reductions. Writes packed g_CP.
// ---------------------------------------------------------------------------
__global__ void __launch_bounds__(256) update_kernel() {
    const int k = blockIdx.x >> 2;
    const int d0 = (blockIdx.x & 3) << 4;
    const int tid = threadIdx.x;
    __shared__ float sden[256];
    __shared__ float sacc[256];

    // denom: 256 threads each grab one partial of colsum(r)
    sden[tid] = g_partR[tid][k];
    __syncthreads();
#pragma unroll
    for (int o = 128; o > 0; o >>= 1) {
        if (tid < o) sden[tid] += sden[tid + o];
        __syncthreads();
    }
    const float denom = sden[0] + 1e-8f;

    // partC: d = d0 + (tid&15) (lane-consecutive => coalesced), s = tid>>4 over b
    const int d = d0 + (tid & 15);
    const int s = tid >> 4;
    float acc = 0.f;
#pragma unroll
    for (int j = 0; j < 16; j++) acc += g_partC[s * 16 + j][k * DLAT + d];
    sacc[tid] = acc;
    __syncthreads();
#pragma unroll
    for (int o = 128; o >= 16; o >>= 1) {
        if (tid < o) sacc[tid] += sacc[tid + o];
        __syncthreads();
    }
    if (tid < 16) {
        const int dd = d0 + tid;
        g_CP[(dd >> 1) * 128 + k * 2 + (dd & 1)] = sacc[tid] / denom;
    }
}

__global__ void finalize_kernel(float* out) {
    out[0] = g_decSum * (1.f / ((float)NROWS * (float)DDATA))
           + 0.001f * g_lossSum * (1.f / (float)NROWS);
}

// ---------------------------------------------------------------------------
extern "C" void kernel_launch(void* const* d_in, const int* in_sizes, int n_in,
                              void* d_out, int out_size) {
    const float* X   = (const float*)d_in[0];
    const float* enc = (const float*)d_in[1];
    const float* dec = (const float*)d_in[2];
    float* out = (float*)d_out;

    init_kernel<<<NROWS / 256, 256>>>(enc);

    const int n4 = NROWS * DDATA / 4;  // 8,388,608 float4s
    decoder_kernel<<<1024, 256>>>((const float4*)X, (const float4*)dec, n4);

    for (int it = 0; it < NITERS; it++) {
        kmeans_iter<<<NB, 256>>>(enc, it == NITERS - 1 ? 1 : 0);
        if (it < NITERS - 1) update_kernel<<<NB, 256>>>();
    }

    finalize_kernel<<<1, 1>>>(out);
}

// round 11
// speedup vs baseline: 1.5125x; 1.3736x over previous
#include <cuda_runtime.h>
#include <cstdint>

// Problem constants (fixed shapes for ClusterLoss_82317343195278)
#define NROWS 65536
#define DLAT  64
#define KC    64
#define DDATA 512
#define NB    256   // kmeans blocks; TPB tiles of 128 rows each
#define TPB   2
#define NITERS 10

// ---- strides (in floats) ----
#define SE 68   // enc hi/lo tiles: conflict-free for GEMM1 A-frags (row varies by gid)
#define SC 68   // C hi/lo tiles:   conflict-free for GEMM1 B-frags
#define SR 72   // r  hi/lo tiles:  conflict-free for GEMM2 A-frags (row varies by tig)

// ---- dynamic smem layout (bytes) ----
#define SM_EHI  0u
#define SM_ELO  (SM_EHI + 128u * SE * 4u)        // 34816
#define SM_CHI  (SM_ELO + 128u * SE * 4u)        // 69632
#define SM_CLO  (SM_CHI + 64u * SC * 4u)         // 87040
#define SM_RHI  (SM_CLO + 64u * SC * 4u)         // 104448
#define SM_RLO  (SM_RHI + 128u * SR * 4u)        // 141312
#define SM_SC2  (SM_RLO + 128u * SR * 4u)        // 178176
#define SM_SRS  (SM_SC2 + 256u)                  // 178432
#define SM_SRED (SM_SRS + 256u)                  // 178688
#define SM_TOTAL (SM_SRED + 1024u)               // 179712

// ---- tf32 helpers ----
__device__ __forceinline__ uint32_t tf32b(float x) {
    uint32_t u;
    asm("cvt.rna.tf32.f32 %0, %1;" : "=r"(u) : "f"(x));
    return u;
}
__device__ __forceinline__ void hilo(float v, uint32_t& h, uint32_t& l) {
    h = tf32b(v);
    l = tf32b(v - __uint_as_float(h));
}
// mma.sync m16n8k8 tf32: D += A*B (D,C same regs)
__device__ __forceinline__ void mma8(float* d, const uint32_t* a, const uint32_t* b) {
    asm volatile(
        "mma.sync.aligned.m16n8k8.row.col.f32.tf32.tf32.f32 "
        "{%0,%1,%2,%3}, {%4,%5,%6,%7}, {%8,%9}, {%0,%1,%2,%3};"
        : "+f"(d[0]), "+f"(d[1]), "+f"(d[2]), "+f"(d[3])
        : "r"(a[0]), "r"(a[1]), "r"(a[2]), "r"(a[3]), "r"(b[0]), "r"(b[1]));
}

// ---- global scratch ----
__device__ __align__(16) float g_C[KC * DLAT];          // centroids [k][d]
__device__ __align__(16) float g_x2[NROWS];
__device__ __align__(16) float g_partC[NB][KC * DLAT];  // [b][k*64+d]
__device__ __align__(16) float g_partR[NB][KC];
__device__ float g_lossSum;
__device__ float g_decSum;

// ---------------------------------------------------------------------------
__global__ void init_kernel(const float* __restrict__ enc) {
    int g = blockIdx.x * blockDim.x + threadIdx.x;
    const float4* p = reinterpret_cast<const float4*>(enc) + (size_t)g * (DLAT / 4);
    float s = 0.f;
#pragma unroll
    for (int i = 0; i < DLAT / 4; i++) {
        float4 v = p[i];
        s += v.x * v.x + v.y * v.y + v.z * v.z + v.w * v.w;
    }
    g_x2[g] = s;
    if (g < KC * DLAT) g_C[g] = enc[g];
    if (g == 0) { g_lossSum = 0.f; g_decSum = 0.f; }
}

__global__ void decoder_kernel(const float4* __restrict__ X,
                               const float4* __restrict__ Dc, int n4) {
    int i = blockIdx.x * blockDim.x + threadIdx.x;
    int stride = gridDim.x * blockDim.x;
    float s = 0.f;
    for (; i < n4; i += stride) {
        float4 a = X[i], b = Dc[i];
        float dx = a.x - b.x, dy = a.y - b.y, dz = a.z - b.z, dw = a.w - b.w;
        s += dx * dx + dy * dy + dz * dz + dw * dw;
    }
    __shared__ float red[256];
    red[threadIdx.x] = s;
    __syncthreads();
#pragma unroll
    for (int o = 128; o > 0; o >>= 1) {
        if (threadIdx.x < o) red[threadIdx.x] += red[threadIdx.x + o];
        __syncthreads();
    }
    if (threadIdx.x == 0) atomicAdd(&g_decSum, red[0]);
}

// ---------------------------------------------------------------------------
// kmeans iteration: both GEMMs on mma.sync tf32 with 3-term split.
// 8 warps; GEMM1: warp w owns rows [16w,16w+16) x all 64 clusters.
// GEMM2: warp w owns clusters [(w&3)*16, +16) x d-tiles [(w>>2)*32, +32).
// ---------------------------------------------------------------------------
__global__ void __launch_bounds__(256, 1)
kmeans_iter(const float* __restrict__ enc, int doLoss) {
    extern __shared__ __align__(16) char smem[];
    uint32_t* sEhi = (uint32_t*)(smem + SM_EHI);
    uint32_t* sElo = (uint32_t*)(smem + SM_ELO);
    uint32_t* sChi = (uint32_t*)(smem + SM_CHI);
    uint32_t* sClo = (uint32_t*)(smem + SM_CLO);
    uint32_t* sRhi = (uint32_t*)(smem + SM_RHI);
    uint32_t* sRlo = (uint32_t*)(smem + SM_RLO);
    float* sc2  = (float*)(smem + SM_SC2);
    float* srs  = (float*)(smem + SM_SRS);
    float* sred = (float*)(smem + SM_SRED);

    const int tid = threadIdx.x;
    const int w = tid >> 5, lane = tid & 31;
    const int gid = lane >> 2, tig = lane & 3;

    // ---- load C hi/lo (stride SC) + c2 + zero srs ----
#pragma unroll
    for (int i = 0; i < 4; i++) {
        int idx = tid + i * 256;             // over 1024 float4
        int k = idx >> 4, d4 = (idx & 15) * 4;
        float4 c = *(const float4*)&g_C[k * DLAT + d4];
        uint32_t h0, l0, h1, l1, h2, l2, h3, l3;
        hilo(c.x, h0, l0); hilo(c.y, h1, l1); hilo(c.z, h2, l2); hilo(c.w, h3, l3);
        uint32_t off = k * SC + d4;
        *(uint4*)&sChi[off] = make_uint4(h0, h1, h2, h3);
        *(uint4*)&sClo[off] = make_uint4(l0, l1, l2, l3);
    }
    if (tid < KC) {
        float s = 0.f;
        const float4* cr = (const float4*)&g_C[tid * DLAT];
#pragma unroll
        for (int i = 0; i < 16; i++) {
            float4 c = cr[i];
            s += c.x * c.x + c.y * c.y + c.z * c.z + c.w * c.w;
        }
        sc2[tid] = s;
        srs[tid] = 0.f;
    }

    float acc2[4][4];
#pragma unroll
    for (int j = 0; j < 4; j++)
#pragma unroll
        for (int i = 0; i < 4; i++) acc2[j][i] = 0.f;
    float lossAcc = 0.f;

#pragma unroll 1
    for (int t = 0; t < TPB; t++) {
        const int rowBase = (blockIdx.x * TPB + t) * 128;
        __syncthreads();  // C stores (t=0) / previous GEMM2 reads done

        // ---- load enc tile hi/lo (stride SE) ----
        {
            const float4* src = (const float4*)(enc + (size_t)rowBase * DLAT);
#pragma unroll
            for (int i = 0; i < 8; i++) {
                int idx = tid + i * 256;     // over 2048 float4
                int row = idx >> 4, d4 = (idx & 15) * 4;
                float4 e = src[idx];
                uint32_t h0, l0, h1, l1, h2, l2, h3, l3;
                hilo(e.x, h0, l0); hilo(e.y, h1, l1); hilo(e.z, h2, l2); hilo(e.w, h3, l3);
                uint32_t off = row * SE + d4;
                *(uint4*)&sEhi[off] = make_uint4(h0, h1, h2, h3);
                *(uint4*)&sElo[off] = make_uint4(l0, l1, l2, l3);
            }
        }
        __syncthreads();

        // ---- GEMM1: rows [16w,16w+16) x 64 clusters, K=64 in 8 chunks ----
        float acc1[8][4];
#pragma unroll
        for (int n = 0; n < 8; n++)
#pragma unroll
            for (int i = 0; i < 4; i++) acc1[n][i] = 0.f;
        const int r0 = w * 16;
#pragma unroll
        for (int dc = 0; dc < 8; dc++) {
            uint32_t ah[4], al[4];
            const int ab = (r0 + gid) * SE + dc * 8 + tig;
            ah[0] = sEhi[ab];            al[0] = sElo[ab];
            ah[1] = sEhi[ab + 8 * SE];   al[1] = sElo[ab + 8 * SE];
            ah[2] = sEhi[ab + 4];        al[2] = sElo[ab + 4];
            ah[3] = sEhi[ab + 8 * SE + 4]; al[3] = sElo[ab + 8 * SE + 4];
#pragma unroll
            for (int n = 0; n < 8; n++) {
                uint32_t bh[2], bl[2];
                const int bb = (n * 8 + gid) * SC + dc * 8 + tig;
                bh[0] = sChi[bb];     bh[1] = sChi[bb + 4];
                bl[0] = sClo[bb];     bl[1] = sClo[bb + 4];
                mma8(acc1[n], ah, bh);
                mma8(acc1[n], ah, bl);
                mma8(acc1[n], al, bh);
            }
        }

        // ---- epilogue: d2, softmax (quad shuffle), loss, r hi/lo, colsums ----
        {
            const int rowA = rowBase + r0 + gid, rowB = rowA + 8;
            const float x2a = g_x2[rowA], x2b = g_x2[rowB];
            float d2a[16], d2b[16];
#pragma unroll
            for (int n = 0; n < 8; n++) {
                const float c20 = sc2[n * 8 + 2 * tig];
                const float c21 = sc2[n * 8 + 2 * tig + 1];
                float v;
                v = x2a + c20 - 2.f * acc1[n][0]; d2a[2 * n]     = v > 0.f ? v : 0.f;
                v = x2a + c21 - 2.f * acc1[n][1]; d2a[2 * n + 1] = v > 0.f ? v : 0.f;
                v = x2b + c20 - 2.f * acc1[n][2]; d2b[2 * n]     = v > 0.f ? v : 0.f;
                v = x2b + c21 - 2.f * acc1[n][3]; d2b[2 * n + 1] = v > 0.f ? v : 0.f;
            }
            float mna = d2a[0], mnb = d2b[0];
#pragma unroll
            for (int i = 1; i < 16; i++) { mna = fminf(mna, d2a[i]); mnb = fminf(mnb, d2b[i]); }
            mna = fminf(mna, __shfl_xor_sync(0xffffffffu, mna, 1));
            mna = fminf(mna, __shfl_xor_sync(0xffffffffu, mna, 2));
            mnb = fminf(mnb, __shfl_xor_sync(0xffffffffu, mnb, 1));
            mnb = fminf(mnb, __shfl_xor_sync(0xffffffffu, mnb, 2));
            float ra[16], rb[16], esa = 0.f, esb = 0.f;
#pragma unroll
            for (int i = 0; i < 16; i++) {
                ra[i] = __expf(mna - d2a[i]); esa += ra[i];
                rb[i] = __expf(mnb - d2b[i]); esb += rb[i];
            }
            esa += __shfl_xor_sync(0xffffffffu, esa, 1);
            esa += __shfl_xor_sync(0xffffffffu, esa, 2);
            esb += __shfl_xor_sync(0xffffffffu, esb, 1);
            esb += __shfl_xor_sync(0xffffffffu, esb, 2);
            const float inva = __fdividef(1.f, esa);
            const float invb = __fdividef(1.f, esb);
            float lsa = 0.f, lsb = 0.f;
#pragma unroll
            for (int i = 0; i < 16; i++) {
                ra[i] *= inva; lsa += ra[i] * d2a[i];
                rb[i] *= invb; lsb += rb[i] * d2b[i];
            }
            if (doLoss) {
                lsa += __shfl_xor_sync(0xffffffffu, lsa, 1);
                lsa += __shfl_xor_sync(0xffffffffu, lsa, 2);
                lsb += __shfl_xor_sync(0xffffffffu, lsb, 1);
                lsb += __shfl_xor_sync(0xffffffffu, lsb, 2);
                if (tig == 0) lossAcc += lsa + lsb;
            }
            // store r hi/lo (stride SR)
            const int rlA = r0 + gid, rlB = rlA + 8;
#pragma unroll
            for (int n = 0; n < 8; n++) {
                const int col = n * 8 + 2 * tig;
                uint32_t h0, l0, h1, l1;
                hilo(ra[2 * n], h0, l0); hilo(ra[2 * n + 1], h1, l1);
                *(uint2*)&sRhi[rlA * SR + col] = make_uint2(h0, h1);
                *(uint2*)&sRlo[rlA * SR + col] = make_uint2(l0, l1);
                hilo(rb[2 * n], h0, l0); hilo(rb[2 * n + 1], h1, l1);
                *(uint2*)&sRhi[rlB * SR + col] = make_uint2(h0, h1);
                *(uint2*)&sRlo[rlB * SR + col] = make_uint2(l0, l1);
            }
            // column sums of r over this warp's 16 rows -> shared atomics
            float cs[16];
#pragma unroll
            for (int i = 0; i < 16; i++) cs[i] = ra[i] + rb[i];
#pragma unroll
            for (int i = 0; i < 16; i++) {
                cs[i] += __shfl_xor_sync(0xffffffffu, cs[i], 4);
                cs[i] += __shfl_xor_sync(0xffffffffu, cs[i], 8);
                cs[i] += __shfl_xor_sync(0xffffffffu, cs[i], 16);
            }
            if (gid == 0) {
#pragma unroll
                for (int n = 0; n < 8; n++) {
                    atomicAdd(&srs[n * 8 + 2 * tig],     cs[2 * n]);
                    atomicAdd(&srs[n * 8 + 2 * tig + 1], cs[2 * n + 1]);
                }
            }
        }
        __syncthreads();  // all r tiles written before GEMM2 reads

        // ---- GEMM2: clusters [(w&3)*16,+16) x d [(w>>2)*32,+32), K=128 rows ----
        {
            const int m0 = (w & 3) * 16;
            const int nb4 = (w >> 2) * 4;
#pragma unroll
            for (int rc = 0; rc < 16; rc++) {
                uint32_t ah[4], al[4];
                const int ar = (rc * 8 + tig) * SR + m0 + gid;
                const int ar4 = ar + 4 * SR;
                ah[0] = sRhi[ar];      al[0] = sRlo[ar];
                ah[1] = sRhi[ar + 8];  al[1] = sRlo[ar + 8];
                ah[2] = sRhi[ar4];     al[2] = sRlo[ar4];
                ah[3] = sRhi[ar4 + 8]; al[3] = sRlo[ar4 + 8];
#pragma unroll
                for (int j = 0; j < 4; j++) {
                    const int n0 = (nb4 + j) * 8;
                    uint32_t bh[2], bl[2];
                    const int be = (rc * 8 + tig) * SE + n0 + gid;
                    bh[0] = sEhi[be];          bh[1] = sEhi[be + 4 * SE];
                    bl[0] = sElo[be];          bl[1] = sElo[be + 4 * SE];
                    mma8(acc2[j], ah, bh);
                    mma8(acc2[j], ah, bl);
                    mma8(acc2[j], al, bh);
                }
            }
        }
    }

    // ---- write per-block partials ----
    {
        const int m0 = (w & 3) * 16;
        const int nb4 = (w >> 2) * 4;
#pragma unroll
        for (int j = 0; j < 4; j++) {
            const int n0 = (nb4 + j) * 8;
            const int kA = m0 + gid, kB = kA + 8;
            const int col = n0 + 2 * tig;
            *(float2*)&g_partC[blockIdx.x][kA * DLAT + col] =
                make_float2(acc2[j][0], acc2[j][1]);
            *(float2*)&g_partC[blockIdx.x][kB * DLAT + col] =
                make_float2(acc2[j][2], acc2[j][3]);
        }
    }
    __syncthreads();
    if (tid < KC) g_partR[blockIdx.x][tid] = srs[tid];

    if (doLoss) {
        sred[tid] = lossAcc;
        __syncthreads();
        for (int o = 128; o > 0; o >>= 1) {
            if (tid < o) sred[tid] += sred[tid + o];
            __syncthreads();
        }
        if (tid == 0) atomicAdd(&g_lossSum, sred[0]);
    }
}

// ---------------------------------------------------------------------------
// Centroid update: 256 blocks x 256 threads, writes plain g_C[k][d].
// ---------------------------------------------------------------------------
__global__ void __launch_bounds__(256) update_kernel() {
    const int k = blockIdx.x >> 2;
    const int d0 = (blockIdx.x & 3) << 4;
    const int tid = threadIdx.x;
    __shared__ float sden[256];
    __shared__ float sacc[256];

    sden[tid] = g_partR[tid][k];
    __syncthreads();
#pragma unroll
    for (int o = 128; o > 0; o >>= 1) {
        if (tid < o) sden[tid] += sden[tid + o];
        __syncthreads();
    }
    const float denom = sden[0] + 1e-8f;

    const int d = d0 + (tid & 15);
    const int s = tid >> 4;
    float acc = 0.f;
#pragma unroll
    for (int j = 0; j < 16; j++) acc += g_partC[s * 16 + j][k * DLAT + d];
    sacc[tid] = acc;
    __syncthreads();
#pragma unroll
    for (int o = 128; o >= 16; o >>= 1) {
        if (tid < o) sacc[tid] += sacc[tid + o];
        __syncthreads();
    }
    if (tid < 16) g_C[k * DLAT + d0 + tid] = sacc[tid] / denom;
}

__global__ void finalize_kernel(float* out) {
    out[0] = g_decSum * (1.f / ((float)NROWS * (float)DDATA))
           + 0.001f * g_lossSum * (1.f / (float)NROWS);
}

// ---------------------------------------------------------------------------
extern "C" void kernel_launch(void* const* d_in, const int* in_sizes, int n_in,
                              void* d_out, int out_size) {
    const float* X   = (const float*)d_in[0];
    const float* enc = (const float*)d_in[1];
    const float* dec = (const float*)d_in[2];
    float* out = (float*)d_out;

    cudaFuncSetAttribute(kmeans_iter, cudaFuncAttributeMaxDynamicSharedMemorySize,
                         SM_TOTAL);

    init_kernel<<<NROWS / 256, 256>>>(enc);

    const int n4 = NROWS * DDATA / 4;
    decoder_kernel<<<1024, 256>>>((const float4*)X, (const float4*)dec, n4);

    for (int it = 0; it < NITERS; it++) {
        kmeans_iter<<<NB, 256, SM_TOTAL>>>(enc, it == NITERS - 1 ? 1 : 0);
        if (it < NITERS - 1) update_kernel<<<NB, 256>>>();
    }

    finalize_kernel<<<1, 1>>>(out);
}

// round 12
// speedup vs baseline: 2.4455x; 1.6169x over previous
#include <cuda_runtime.h>
#include <cstdint>

// Problem constants (fixed shapes for ClusterLoss_82317343195278)
#define NROWS 65536
#define DLAT  64
#define KC    64
#define DDATA 512
#define NB    256   // kmeans blocks; TPB tiles of 128 rows each
#define TPB   2
#define NITERS 10

// ---- strides (in floats) ----
// SE=76: GEMM1 A (gid*76+tig -> gid*12+tig mod32 unique) AND GEMM2 B
//        (tig*76+gid -> tig*12+gid mod32 unique) both conflict-free.
#define SE 76
#define SC 68   // GEMM1 B: gid*68+tig -> gid*4+tig mod32 unique
#define SR 72   // GEMM2 A: tig*72+gid -> tig*8+gid mod32 unique

// ---- dynamic smem layout (bytes) ----
#define SM_E    0u
#define SM_C    (SM_E + 128u * SE * 4u)          // 38912
#define SM_R    (SM_C + 64u * SC * 4u)           // 56320
#define SM_SC2  (SM_R + 128u * SR * 4u)          // 93184
#define SM_SRS  (SM_SC2 + 256u)                  // 93440
#define SM_SRED (SM_SRS + 256u)                  // 93696
#define SM_TOTAL (SM_SRED + 1024u)               // 94720  (2 CTAs/SM)

// ---- tf32 helpers ----
__device__ __forceinline__ uint32_t tf32b(float x) {
    uint32_t u;
    asm("cvt.rna.tf32.f32 %0, %1;" : "=r"(u) : "f"(x));
    return u;
}
// mma.sync m16n8k8 tf32: D += A*B (D,C same regs)
__device__ __forceinline__ void mma8(float* d, const uint32_t* a, const uint32_t* b) {
    asm volatile(
        "mma.sync.aligned.m16n8k8.row.col.f32.tf32.tf32.f32 "
        "{%0,%1,%2,%3}, {%4,%5,%6,%7}, {%8,%9}, {%0,%1,%2,%3};"
        : "+f"(d[0]), "+f"(d[1]), "+f"(d[2]), "+f"(d[3])
        : "r"(a[0]), "r"(a[1]), "r"(a[2]), "r"(a[3]), "r"(b[0]), "r"(b[1]));
}

// ---- global scratch ----
__device__ __align__(16) float g_C[KC * DLAT];          // centroids [k][d]
__device__ __align__(16) float g_x2[NROWS];
__device__ __align__(16) float g_partC[NB][KC * DLAT];  // [b][k*64+d]
__device__ __align__(16) float g_partR[NB][KC];
__device__ float g_lossSum;
__device__ float g_decSum;

// ---------------------------------------------------------------------------
__global__ void init_kernel(const float* __restrict__ enc) {
    int g = blockIdx.x * blockDim.x + threadIdx.x;
    const float4* p = reinterpret_cast<const float4*>(enc) + (size_t)g * (DLAT / 4);
    float s = 0.f;
#pragma unroll
    for (int i = 0; i < DLAT / 4; i++) {
        float4 v = p[i];
        s += v.x * v.x + v.y * v.y + v.z * v.z + v.w * v.w;
    }
    g_x2[g] = s;
    if (g < KC * DLAT) g_C[g] = enc[g];
    if (g == 0) { g_lossSum = 0.f; g_decSum = 0.f; }
}

__global__ void decoder_kernel(const float4* __restrict__ X,
                               const float4* __restrict__ Dc, int n4) {
    int i = blockIdx.x * blockDim.x + threadIdx.x;
    int stride = gridDim.x * blockDim.x;
    float s = 0.f;
    for (; i < n4; i += stride) {
        float4 a = X[i], b = Dc[i];
        float dx = a.x - b.x, dy = a.y - b.y, dz = a.z - b.z, dw = a.w - b.w;
        s += dx * dx + dy * dy + dz * dz + dw * dw;
    }
    __shared__ float red[256];
    red[threadIdx.x] = s;
    __syncthreads();
#pragma unroll
    for (int o = 128; o > 0; o >>= 1) {
        if (threadIdx.x < o) red[threadIdx.x] += red[threadIdx.x + o];
        __syncthreads();
    }
    if (threadIdx.x == 0) atomicAdd(&g_decSum, red[0]);
}

// ---------------------------------------------------------------------------
// kmeans iteration: both GEMMs on mma.sync tf32, single-pass (no split).
// 8 warps; GEMM1: warp w owns rows [16w,16w+16) x all 64 clusters.
// GEMM2: warp w owns clusters [(w&3)*16,+16) x d-tiles [(w>>2)*32,+32).
// Last iteration (doLoss): loss only, GEMM2/partials skipped.
// ---------------------------------------------------------------------------
__global__ void __launch_bounds__(256, 2)
kmeans_iter(const float* __restrict__ enc, int doLoss) {
    extern __shared__ __align__(16) char smem[];
    uint32_t* sE = (uint32_t*)(smem + SM_E);
    uint32_t* sC = (uint32_t*)(smem + SM_C);
    uint32_t* sR = (uint32_t*)(smem + SM_R);
    float* sc2  = (float*)(smem + SM_SC2);
    float* srs  = (float*)(smem + SM_SRS);
    float* sred = (float*)(smem + SM_SRED);

    const int tid = threadIdx.x;
    const int w = tid >> 5, lane = tid & 31;
    const int gid = lane >> 2, tig = lane & 3;

    // ---- load C as tf32 (stride SC) + c2 (fp32) + zero srs ----
#pragma unroll
    for (int i = 0; i < 4; i++) {
        int idx = tid + i * 256;             // over 1024 float4
        int k = idx >> 4, d4 = (idx & 15) * 4;
        float4 c = *(const float4*)&g_C[k * DLAT + d4];
        *(uint4*)&sC[k * SC + d4] =
            make_uint4(tf32b(c.x), tf32b(c.y), tf32b(c.z), tf32b(c.w));
    }
    if (tid < KC) {
        float s = 0.f;
        const float4* cr = (const float4*)&g_C[tid * DLAT];
#pragma unroll
        for (int i = 0; i < 16; i++) {
            float4 c = cr[i];
            s += c.x * c.x + c.y * c.y + c.z * c.z + c.w * c.w;
        }
        sc2[tid] = s;
        srs[tid] = 0.f;
    }

    float acc2[4][4];
#pragma unroll
    for (int j = 0; j < 4; j++)
#pragma unroll
        for (int i = 0; i < 4; i++) acc2[j][i] = 0.f;
    float lossAcc = 0.f;

#pragma unroll 1
    for (int t = 0; t < TPB; t++) {
        const int rowBase = (blockIdx.x * TPB + t) * 128;
        __syncthreads();  // C stores (t=0) / previous GEMM2 reads done

        // ---- load enc tile as tf32 (stride SE) ----
        {
            const float4* src = (const float4*)(enc + (size_t)rowBase * DLAT);
#pragma unroll
            for (int i = 0; i < 8; i++) {
                int idx = tid + i * 256;     // over 2048 float4
                int row = idx >> 4, d4 = (idx & 15) * 4;
                float4 e = src[idx];
                *(uint4*)&sE[row * SE + d4] =
                    make_uint4(tf32b(e.x), tf32b(e.y), tf32b(e.z), tf32b(e.w));
            }
        }
        __syncthreads();

        // ---- GEMM1: rows [16w,16w+16) x 64 clusters, K=64 in 8 chunks ----
        float acc1[8][4];
#pragma unroll
        for (int n = 0; n < 8; n++)
#pragma unroll
            for (int i = 0; i < 4; i++) acc1[n][i] = 0.f;
        const int r0 = w * 16;
#pragma unroll
        for (int dc = 0; dc < 8; dc++) {
            uint32_t a[4];
            const int ab = (r0 + gid) * SE + dc * 8 + tig;
            a[0] = sE[ab];
            a[1] = sE[ab + 8 * SE];
            a[2] = sE[ab + 4];
            a[3] = sE[ab + 8 * SE + 4];
#pragma unroll
            for (int n = 0; n < 8; n++) {
                uint32_t b[2];
                const int bb = (n * 8 + gid) * SC + dc * 8 + tig;
                b[0] = sC[bb];
                b[1] = sC[bb + 4];
                mma8(acc1[n], a, b);
            }
        }

        // ---- epilogue: d2 in place of acc1, softmax (quad shuffle), loss,
        //      r -> sR (tf32), column sums ----
        {
            const int rowA = rowBase + r0 + gid;
            const float x2a = g_x2[rowA], x2b = g_x2[rowA + 8];
#pragma unroll
            for (int n = 0; n < 8; n++) {
                const float c20 = sc2[n * 8 + 2 * tig];
                const float c21 = sc2[n * 8 + 2 * tig + 1];
                float v;
                v = x2a + c20 - 2.f * acc1[n][0]; acc1[n][0] = v > 0.f ? v : 0.f;
                v = x2a + c21 - 2.f * acc1[n][1]; acc1[n][1] = v > 0.f ? v : 0.f;
                v = x2b + c20 - 2.f * acc1[n][2]; acc1[n][2] = v > 0.f ? v : 0.f;
                v = x2b + c21 - 2.f * acc1[n][3]; acc1[n][3] = v > 0.f ? v : 0.f;
            }
            float cs[16];
            const int rlA = r0 + gid;
            // two half-rows: h=0 -> rowA (acc1[n][0..1]), h=1 -> rowB (acc1[n][2..3])
#pragma unroll
            for (int h = 0; h < 2; h++) {
                float mn = 3.4e38f;
#pragma unroll
                for (int n = 0; n < 8; n++)
                    mn = fminf(mn, fminf(acc1[n][2 * h], acc1[n][2 * h + 1]));
                mn = fminf(mn, __shfl_xor_sync(0xffffffffu, mn, 1));
                mn = fminf(mn, __shfl_xor_sync(0xffffffffu, mn, 2));
                float es = 0.f;
#pragma unroll
                for (int n = 0; n < 8; n++)
                    es += __expf(mn - acc1[n][2 * h]) + __expf(mn - acc1[n][2 * h + 1]);
                es += __shfl_xor_sync(0xffffffffu, es, 1);
                es += __shfl_xor_sync(0xffffffffu, es, 2);
                const float inv = __fdividef(1.f, es);
                float ls = 0.f;
#pragma unroll
                for (int n = 0; n < 8; n++) {
                    float d20 = acc1[n][2 * h], d21 = acc1[n][2 * h + 1];
                    float rr0 = __expf(mn - d20) * inv;
                    float rr1 = __expf(mn - d21) * inv;
                    ls += rr0 * d20 + rr1 * d21;
                    if (h == 0) { cs[2 * n] = rr0; cs[2 * n + 1] = rr1; }
                    else        { cs[2 * n] += rr0; cs[2 * n + 1] += rr1; }
                    if (!doLoss)
                        *(uint2*)&sR[(rlA + 8 * h) * SR + n * 8 + 2 * tig] =
                            make_uint2(tf32b(rr0), tf32b(rr1));
                }
                if (doLoss) {
                    ls += __shfl_xor_sync(0xffffffffu, ls, 1);
                    ls += __shfl_xor_sync(0xffffffffu, ls, 2);
                    if (tig == 0) lossAcc += ls;
                }
            }
            if (!doLoss) {
                // column sums of r over this warp's 16 rows -> shared atomics
#pragma unroll
                for (int i = 0; i < 16; i++) {
                    cs[i] += __shfl_xor_sync(0xffffffffu, cs[i], 4);
                    cs[i] += __shfl_xor_sync(0xffffffffu, cs[i], 8);
                    cs[i] += __shfl_xor_sync(0xffffffffu, cs[i], 16);
                }
                if (gid == 0) {
#pragma unroll
                    for (int n = 0; n < 8; n++) {
                        atomicAdd(&srs[n * 8 + 2 * tig],     cs[2 * n]);
                        atomicAdd(&srs[n * 8 + 2 * tig + 1], cs[2 * n + 1]);
                    }
                }
            }
        }

        if (!doLoss) {
            __syncthreads();  // all r tiles written before GEMM2 reads

            // ---- GEMM2: clusters [(w&3)*16,+16) x d [(w>>2)*32,+32), K=128 ----
            const int m0 = (w & 3) * 16;
            const int nb4 = (w >> 2) * 4;
#pragma unroll
            for (int rc = 0; rc < 16; rc++) {
                uint32_t a[4];
                const int ar = (rc * 8 + tig) * SR + m0 + gid;
                const int ar4 = ar + 4 * SR;
                a[0] = sR[ar];
                a[1] = sR[ar + 8];
                a[2] = sR[ar4];
                a[3] = sR[ar4 + 8];
#pragma unroll
                for (int j = 0; j < 4; j++) {
                    uint32_t b[2];
                    const int be = (rc * 8 + tig) * SE + (nb4 + j) * 8 + gid;
                    b[0] = sE[be];
                    b[1] = sE[be + 4 * SE];
                    mma8(acc2[j], a, b);
                }
            }
        }
    }

    if (!doLoss) {
        // ---- write per-block partials ----
        const int m0 = (w & 3) * 16;
        const int nb4 = (w >> 2) * 4;
#pragma unroll
        for (int j = 0; j < 4; j++) {
            const int n0 = (nb4 + j) * 8;
            const int kA = m0 + gid, kB = kA + 8;
            const int col = n0 + 2 * tig;
            *(float2*)&g_partC[blockIdx.x][kA * DLAT + col] =
                make_float2(acc2[j][0], acc2[j][1]);
            *(float2*)&g_partC[blockIdx.x][kB * DLAT + col] =
                make_float2(acc2[j][2], acc2[j][3]);
        }
        __syncthreads();
        if (tid < KC) g_partR[blockIdx.x][tid] = srs[tid];
    } else {
        sred[tid] = lossAcc;
        __syncthreads();
        for (int o = 128; o > 0; o >>= 1) {
            if (tid < o) sred[tid] += sred[tid + o];
            __syncthreads();
        }
        if (tid == 0) atomicAdd(&g_lossSum, sred[0]);
    }
}

// ---------------------------------------------------------------------------
// Centroid update: 256 blocks x 256 threads, writes plain g_C[k][d].
// ---------------------------------------------------------------------------
__global__ void __launch_bounds__(256) update_kernel() {
    const int k = blockIdx.x >> 2;
    const int d0 = (blockIdx.x & 3) << 4;
    const int tid = threadIdx.x;
    __shared__ float sden[256];
    __shared__ float sacc[256];

    sden[tid] = g_partR[tid][k];
    __syncthreads();
#pragma unroll
    for (int o = 128; o > 0; o >>= 1) {
        if (tid < o) sden[tid] += sden[tid + o];
        __syncthreads();
    }
    const float denom = sden[0] + 1e-8f;

    const int d = d0 + (tid & 15);
    const int s = tid >> 4;
    float acc = 0.f;
#pragma unroll
    for (int j = 0; j < 16; j++) acc += g_partC[s * 16 + j][k * DLAT + d];
    sacc[tid] = acc;
    __syncthreads();
#pragma unroll
    for (int o = 128; o >= 16; o >>= 1) {
        if (tid < o) sacc[tid] += sacc[tid + o];
        __syncthreads();
    }
    if (tid < 16) g_C[k * DLAT + d0 + tid] = sacc[tid] / denom;
}

__global__ void finalize_kernel(float* out) {
    out[0] = g_decSum * (1.f / ((float)NROWS * (float)DDATA))
           + 0.001f * g_lossSum * (1.f / (float)NROWS);
}

// ---------------------------------------------------------------------------
extern "C" void kernel_launch(void* const* d_in, const int* in_sizes, int n_in,
                              void* d_out, int out_size) {
    const float* X   = (const float*)d_in[0];
    const float* enc = (const float*)d_in[1];
    const float* dec = (const float*)d_in[2];
    float* out = (float*)d_out;

    cudaFuncSetAttribute(kmeans_iter, cudaFuncAttributeMaxDynamicSharedMemorySize,
                         SM_TOTAL);

    init_kernel<<<NROWS / 256, 256>>>(enc);

    const int n4 = NROWS * DDATA / 4;
    decoder_kernel<<<1024, 256>>>((const float4*)X, (const float4*)dec, n4);

    for (int it = 0; it < NITERS; it++) {
        kmeans_iter<<<NB, 256, SM_TOTAL>>>(enc, it == NITERS - 1 ? 1 : 0);
        if (it < NITERS - 1) update_kernel<<<NB, 256>>>();
    }

    finalize_kernel<<<1, 1>>>(out);
}